// round 10
// baseline (speedup 1.0000x reference)
#include <cuda_runtime.h>

#define NPG    1430
#define GENE0  1421
#define NHEADS 9

static const int MAXN = 732160;            // 1430 * 512 nodes
static const int MAXA = 512 * NHEADS * 16; // agg2 accumulator
static const int GCAP = 262144;            // gene-edge list capacity (~37K expected)
static const int BMW  = MAXN / 32;         // bitmap words (22880)

// Scratch (allocation-free: __device__ globals; zero-initialized at load).
// Self-cleaning invariant: every kernel_launch leaves degi/bm/gcount zeroed
// (by k_node1 / k_l2 / k_final respectively), so no upfront zero pass.
__device__ int      g_degi[MAXN];
__device__ float4   g_pk[MAXN];      // {dinv, u, raw, -} packed per node (1 sector)
__device__ float    g_agg2[MAXA];    // layer-2 raw aggregation at gene nodes
__device__ int      g_glist[GCAP];   // edge ids whose dst is a gene node
__device__ int      g_gcount;
__device__ unsigned g_bm[BMW];       // bitmap: S = {gene-edge srcs} U {gene dsts}

// ---------------------------------------------------------------------------
// Pass 1: in-degree count + gene-edge compaction + S-membership bitmap.
// Gene-dst detection is pure arithmetic (v % 1430 >= 1421). For each gene
// edge (~0.63%): record edge id, set bitmap bits for its src and dst.
// Gene-edge id reservation is block-aggregated (one global atomic per block).
// ---------------------------------------------------------------------------
__global__ void k_deg(const int* __restrict__ src, const int* __restrict__ dst,
                      int e4) {
    __shared__ int s_cnt, s_base;
    if (threadIdx.x == 0) s_cnt = 0;
    __syncthreads();

    int i = blockIdx.x * blockDim.x + threadIdx.x;
    int hits[4];
    int c = 0;
    if (i < e4) {
        int4 d = __ldcs((const int4*)dst + i);
        int dd[4] = {d.x, d.y, d.z, d.w};
#pragma unroll
        for (int j = 0; j < 4; j++) {
            unsigned v = (unsigned)dd[j];
            atomicAdd(&g_degi[v], 1);
            unsigned q = v / (unsigned)NPG;
            if (v - q * (unsigned)NPG >= (unsigned)GENE0) {
                int e = i * 4 + j;
                hits[c++] = e;
                unsigned s = (unsigned)__ldg(src + e);
                atomicOr(&g_bm[s >> 5], 1u << (s & 31u));   // src needs t
                atomicOr(&g_bm[v >> 5], 1u << (v & 31u));   // gene dst needs raw
            }
        }
    }

    int my_off = 0;
    if (c) my_off = atomicAdd(&s_cnt, c);
    __syncthreads();
    if (threadIdx.x == 0) s_base = s_cnt ? atomicAdd(&g_gcount, s_cnt) : 0;
    __syncthreads();

    int base = s_base + my_off;
    for (int k = 0; k < c; k++) {
        int p = base + k;
        if (p < GCAP) g_glist[p] = hits[k];
    }
}

// ---------------------------------------------------------------------------
// Per-node: pk = {dinv, u, 0, 0} with dinv = rsqrt(deg+1), u = dinv*x.
// Zeroes agg2 and self-cleans degi (k_node1 is degi's only consumer).
// Each thread writes 4 consecutive nodes = 64B contiguous.
// ---------------------------------------------------------------------------
__global__ void k_node1(const float* __restrict__ x, int n4, int a4) {
    int i = blockIdx.x * blockDim.x + threadIdx.x;
    if (i < a4) ((float4*)g_agg2)[i] = make_float4(0.f, 0.f, 0.f, 0.f);
    if (i >= n4) return;
    int4   dg = ((const int4*)g_degi)[i];
    float4 xv = __ldg((const float4*)x + i);
    float d0 = rsqrtf((float)dg.x + 1.0f);
    float d1 = rsqrtf((float)dg.y + 1.0f);
    float d2 = rsqrtf((float)dg.z + 1.0f);
    float d3 = rsqrtf((float)dg.w + 1.0f);
    g_pk[i * 4 + 0] = make_float4(d0, d0 * xv.x, 0.f, 0.f);
    g_pk[i * 4 + 1] = make_float4(d1, d1 * xv.y, 0.f, 0.f);
    g_pk[i * 4 + 2] = make_float4(d2, d2 * xv.z, 0.f, 0.f);
    g_pk[i * 4 + 3] = make_float4(d3, d3 * xv.w, 0.f, 0.f);
    ((int4*)g_degi)[i] = make_int4(0, 0, 0, 0);       // self-clean for next replay
}

// ---------------------------------------------------------------------------
// Pass 2 (sparsified): pk[dst].raw += pk[src].u ONLY when dst is in S
// (~5.6% of edges). One random access per edge (bitmap word, mostly
// L1-resident); src is loaded SCALAR and only on a hit.
// ---------------------------------------------------------------------------
__global__ void k_scatter(const int* __restrict__ src, const int* __restrict__ dst,
                          int e4) {
    int i = blockIdx.x * blockDim.x + threadIdx.x;
    if (i >= e4) return;
    int4 d4 = __ldcs((const int4*)dst + i);
    int dd[4] = {d4.x, d4.y, d4.z, d4.w};
#pragma unroll
    for (int j = 0; j < 4; j++) {
        unsigned v = (unsigned)dd[j];
        unsigned w = __ldg(&g_bm[v >> 5]);
        if ((w >> (v & 31u)) & 1u) {
            unsigned s = (unsigned)__ldg(src + i * 4 + j);
            float us = __ldg(((const float*)(g_pk + s)) + 1);   // pk[s].u
            atomicAdd(((float*)(g_pk + v)) + 2, us);            // pk[v].raw
        }
    }
}

// ---------------------------------------------------------------------------
// Pass 3: layer-2 scatter restricted to gene-destination edges.
// 16 lanes per edge; lane c computes channel c and issues ONE atomic (the 16
// lane-atomics coalesce into one 64B-line wavefront per edge). ONE packed
// float4 load fetches {dinv, u, raw} of the source (was 3 random sectors).
// Grid sized so expected cnt fits in one iteration. Also zeroes the bitmap.
// ---------------------------------------------------------------------------
__global__ void k_l2(const int* __restrict__ src, const int* __restrict__ dst,
                     const float* __restrict__ W1, const float* __restrict__ b1,
                     const float* __restrict__ W2) {
    __shared__ float sW1[16], sb1[16], sW2[256];
    int tid = threadIdx.x;
    if (tid < 16) { sW1[tid] = W1[tid]; sb1[tid] = b1[tid]; }
    for (int j = tid; j < 256; j += blockDim.x) sW2[j] = W2[j];
    __syncthreads();

    int flat = blockIdx.x * blockDim.x + tid;
    if (flat < BMW) g_bm[flat] = 0u;           // self-clean for next replay

    int cnt = g_gcount;
    if (cnt > GCAP) cnt = GCAP;

    int lane    = tid & 15;
    int group   = flat >> 4;
    int gstride = (gridDim.x * blockDim.x) >> 4;

    for (int g = group; g < cnt; g += gstride) {
        int e = __ldg(&g_glist[g]);
        int s = __ldg(src + e);
        unsigned d = (unsigned)__ldg(dst + e);
        float4 p = __ldg(&g_pk[s]);            // {dinv, u, raw} in one sector
        float ws = p.x;
        float ts = ws * (p.z + p.y);           // t inline

        float m = 0.f;
#pragma unroll
        for (int k = 0; k < 16; k++) {
            float h = fmaxf(fmaf(ts, sW1[k], sb1[k]), 0.f);
            m = fmaf(h, sW2[k * 16 + lane], m);
        }

        unsigned gq = d / (unsigned)NPG;
        int head = (int)(d - gq * (unsigned)NPG) - GENE0;
        int gi = ((int)gq * NHEADS + head) * 16;
        atomicAdd(&g_agg2[gi + lane], ws * m);
    }
}

// ---------------------------------------------------------------------------
// Final: per gene node, close layer 2 (self loop + scale + b2 + relu),
// then the per-head MLP.  Also zeroes gcount (reader k_l2 has completed).
// ---------------------------------------------------------------------------
__global__ void k_final(const float* __restrict__ W1, const float* __restrict__ b1,
                        const float* __restrict__ W2, const float* __restrict__ b2,
                        const float* __restrict__ fw1, const float* __restrict__ fb1,
                        const float* __restrict__ fw2, const float* __restrict__ fb2,
                        float* __restrict__ out, int G) {
    int tid = blockIdx.x * blockDim.x + threadIdx.x;
    if (tid == 0) g_gcount = 0;                // self-clean for next replay
    if (tid >= G * NHEADS) return;
    int head = tid / G;
    int g    = tid - head * G;
    int node = g * NPG + GENE0 + head;

    float4 p = __ldg(&g_pk[node]);
    float dv = p.x;
    float tn = dv * (p.z + p.y);               // t inline

    float m[16];
#pragma unroll
    for (int c = 0; c < 16; c++) m[c] = 0.f;
#pragma unroll
    for (int k = 0; k < 16; k++) {
        float h = fmaxf(fmaf(tn, __ldg(W1 + k), __ldg(b1 + k)), 0.f);
#pragma unroll
        for (int c = 0; c < 16; c++) m[c] = fmaf(h, __ldg(W2 + k * 16 + c), m[c]);
    }

    int gi = (g * NHEADS + head) * 16;
    float h2[16];
#pragma unroll
    for (int c = 0; c < 16; c++) {
        float a = dv * (g_agg2[gi + c] + dv * m[c]) + __ldg(b2 + c);
        h2[c] = fmaxf(a, 0.f);
    }

    float pred = __ldg(fb2 + head);
#pragma unroll
    for (int j = 0; j < 8; j++) {
        float z = __ldg(fb1 + head * 8 + j);
#pragma unroll
        for (int c = 0; c < 16; c++)
            z = fmaf(h2[c], __ldg(fw1 + head * 128 + c * 8 + j), z);
        z = fmaxf(z, 0.f);
        pred = fmaf(z, __ldg(fw2 + head * 8 + j), pred);
    }
    out[head * G + g] = pred;
}

// ---------------------------------------------------------------------------
extern "C" void kernel_launch(void* const* d_in, const int* in_sizes, int n_in,
                              void* d_out, int out_size) {
    const float* x   = (const float*)d_in[0];
    const int*   ei  = (const int*)  d_in[1];
    const float* W1  = (const float*)d_in[3];
    const float* b1  = (const float*)d_in[4];
    const float* W2  = (const float*)d_in[5];
    const float* b2  = (const float*)d_in[6];
    const float* fw1 = (const float*)d_in[7];
    const float* fb1 = (const float*)d_in[8];
    const float* fw2 = (const float*)d_in[9];
    const float* fb2 = (const float*)d_in[10];
    float* out = (float*)d_out;

    int N = in_sizes[0];             // x is [N,1]   (732160, div by 4)
    int E = in_sizes[1] / 2;         // edge_index is [2,E]  (E div by 4)
    int G = in_sizes[2] / NHEADS;    // y is [G*9]

    const int* src = ei;
    const int* dst = ei + E;

    int n4 = N / 4;
    int e4 = E / 4;
    int a4 = (G * NHEADS * 16) / 4;

    const int B = 256;

    k_deg<<<(e4 + B - 1) / B, B>>>(src, dst, e4);
    k_node1<<<(n4 + B - 1) / B, B>>>(x, n4, a4);
    k_scatter<<<(e4 + B - 1) / B, B>>>(src, dst, e4);
    k_l2<<<2560, B>>>(src, dst, W1, b1, W2);     // 40960 groups >= expected cnt
    k_final<<<(G * NHEADS + 31) / 32, 32>>>(W1, b1, W2, b2, fw1, fb1, fw2, fb2, out, G);
}